// round 16
// baseline (speedup 1.0000x reference)
#include <cuda_runtime.h>
#include <cuda_fp16.h>

// LinearEdgeDecoder, factored + fp16 table + HMMA precompute.
// R15 (= R14 resubmit; prior run died to container flake, no kernel signal):
// cp.async pipeline keeps TWO chunks in flight (R13 waited each chunk to
// completion before committing the next, leaving ~1 load-latency exposed).

#define ASK2 40             // A chunk stride in halves (80B rows, ldmatrix conflict-free)
#define BSK  136            // B chunk stride in halves (272B rows)
#define AST  136            // staging stride in halves
#define NT   256
#define ABUF (128 * ASK2)   // 5120 halves per A stage
#define BBUF (32 * BSK)     // 4352 halves per B stage
#define STAGE_H (ABUF + BBUF)

__device__ int    g_idx_is64;
__device__ __align__(16) __half g_uv[(size_t)131072 * 256];   // node table u|v (64 MB)
__device__ __align__(16) __half g_xh[(size_t)131072 * 128];   // x in fp16 (32 MB)
__device__ __align__(16) __half g_wh[256 * 128];              // W1 in fp16
__device__ __align__(16) __half g_w2h[128];                   // W2 in fp16

__device__ __forceinline__ unsigned h2_bits(__half2 h) {
    return *reinterpret_cast<unsigned*>(&h);
}
__device__ __forceinline__ __half2 bits_h2(unsigned b) {
    return *reinterpret_cast<__half2*>(&b);
}

__device__ __forceinline__ void cp16(unsigned dst, const void* src) {
    asm volatile("cp.async.cg.shared.global [%0], [%1], 16;" :: "r"(dst), "l"(src));
}
__device__ __forceinline__ void cp_commit() {
    asm volatile("cp.async.commit_group;");
}
template <int N>
__device__ __forceinline__ void cp_wait() {
    asm volatile("cp.async.wait_group %0;" :: "n"(N));
}

__device__ __forceinline__ void ldsm_x4(unsigned& r0, unsigned& r1, unsigned& r2, unsigned& r3,
                                        unsigned addr) {
    asm volatile("ldmatrix.sync.aligned.m8n8.x4.shared.b16 {%0,%1,%2,%3}, [%4];"
                 : "=r"(r0), "=r"(r1), "=r"(r2), "=r"(r3) : "r"(addr));
}
__device__ __forceinline__ void ldsm_x4_t(unsigned& r0, unsigned& r1, unsigned& r2, unsigned& r3,
                                          unsigned addr) {
    asm volatile("ldmatrix.sync.aligned.m8n8.x4.trans.shared.b16 {%0,%1,%2,%3}, [%4];"
                 : "=r"(r0), "=r"(r1), "=r"(r2), "=r"(r3) : "r"(addr));
}
__device__ __forceinline__ void mma16816(float* c, const unsigned* a, unsigned b0, unsigned b1) {
    asm volatile(
        "mma.sync.aligned.m16n8k16.row.col.f32.f16.f16.f32 "
        "{%0,%1,%2,%3},{%4,%5,%6,%7},{%8,%9},{%0,%1,%2,%3};"
        : "+f"(c[0]), "+f"(c[1]), "+f"(c[2]), "+f"(c[3])
        : "r"(a[0]), "r"(a[1]), "r"(a[2]), "r"(a[3]), "r"(b0), "r"(b1));
}

// ---------------- one-shot fp16 conversion (+ dtype sniff) ----------------
__global__ __launch_bounds__(256) void convert_fp16(
    const float* __restrict__ x,    // [n_nodes, 128]
    const float* __restrict__ W1,   // [256, 128]
    const float* __restrict__ W2,   // [128]
    const void*  __restrict__ eidx,
    int n_nodes)
{
    long long i0 = ((long long)blockIdx.x * 256 + threadIdx.x) * 2;

    if (blockIdx.x == 0 && threadIdx.x < 32) {
        const long long* p = (const long long*)eidx;
        int bad = 0;
        #pragma unroll
        for (int t = 0; t < 2; ++t) {
            long long vv = p[threadIdx.x * 2 + t];
            if (vv < 0 || vv >= (long long)n_nodes) bad = 1;
        }
        unsigned m = __ballot_sync(0xffffffffu, bad);
        if (threadIdx.x == 0) g_idx_is64 = (m == 0u);
    }

    long long total = (long long)n_nodes * 32;   // float4 count of x
    if (i0 + 1 < total) {
        float4 f0 = ((const float4*)x)[i0];
        float4 f1 = ((const float4*)x)[i0 + 1];
        uint4 pk;
        pk.x = h2_bits(__floats2half2_rn(f0.x, f0.y));
        pk.y = h2_bits(__floats2half2_rn(f0.z, f0.w));
        pk.z = h2_bits(__floats2half2_rn(f1.x, f1.y));
        pk.w = h2_bits(__floats2half2_rn(f1.z, f1.w));
        *(uint4*)((uint2*)g_xh + i0) = pk;
    } else if (i0 < total) {
        float4 f0 = ((const float4*)x)[i0];
        uint2 pk;
        pk.x = h2_bits(__floats2half2_rn(f0.x, f0.y));
        pk.y = h2_bits(__floats2half2_rn(f0.z, f0.w));
        ((uint2*)g_xh)[i0] = pk;
    }
    if (i0 < 8192) {                             // W1 = 8192 float4
        #pragma unroll
        for (int t = 0; t < 2; ++t) {
            float4 f = ((const float4*)W1)[i0 + t];
            uint2 pk;
            pk.x = h2_bits(__floats2half2_rn(f.x, f.y));
            pk.y = h2_bits(__floats2half2_rn(f.z, f.w));
            ((uint2*)g_wh)[i0 + t] = pk;
        }
    }
    if (i0 < 32) {                               // W2 = 32 float4
        #pragma unroll
        for (int t = 0; t < 2; ++t) {
            float4 f = ((const float4*)W2)[i0 + t];
            uint2 pk;
            pk.x = h2_bits(__floats2half2_rn(f.x, f.y));
            pk.y = h2_bits(__floats2half2_rn(f.z, f.w));
            ((uint2*)g_w2h)[i0 + t] = pk;
        }
    }
}

// ---------------- node-table GEMM on tensor cores, 2-deep cp.async pipeline ----------------
// grid = (ceil(n_nodes/128), 2). CTA tile 128 nodes x 128 features,
// K=128 as 4 chunks of 32, double-buffered with 2 loads in flight.
__global__ __launch_bounds__(NT) void precompute_uv(
    const float* __restrict__ b1,   // [128]
    int n_nodes)
{
    __shared__ __align__(16) __half smem_s[2 * STAGE_H];   // 37888 B

    const int tid  = threadIdx.x;
    const int base = blockIdx.x * 128;
    const int half = blockIdx.y;     // 0 -> u (+b1), 1 -> v

    const int rA   = tid >> 1;       // node row 0..127
    const int segA = tid & 1;        // 16-half segment within 32-half chunk row
    int nodeA = base + rA; if (nodeA >= n_nodes) nodeA = 0;
    const int rowB  = tid >> 3;      // k row 0..31
    const int laneB = tid & 7;       // 16-half segment within 128-half row

    const int w    = tid >> 5;
    const int lane = tid & 31;
    const int mw   = (w & 1) * 64;
    const int nw   = (w >> 1) * 32;
    const int lr   = lane & 15;
    const int lc   = (lane >> 4) * 8;

    float acc[4][4][4];
    #pragma unroll
    for (int i = 0; i < 4; ++i)
        #pragma unroll
        for (int j = 0; j < 4; ++j)
            #pragma unroll
            for (int t = 0; t < 4; ++t) acc[i][j][t] = 0.f;

    const unsigned sbase = (unsigned)__cvta_generic_to_shared(smem_s);

    const __half* srcA_base = g_xh + (size_t)nodeA * 128 + segA * 16;
    const __half* srcB_base = g_wh + (size_t)(half * 128 + rowB) * 128 + laneB * 16;
    const unsigned dstA_off = (unsigned)(rA * ASK2 + segA * 16) * 2;
    const unsigned dstB_off = (unsigned)(ABUF + rowB * BSK + laneB * 16) * 2;

    auto load_chunk = [&](int c, int s) {
        unsigned sb = sbase + (unsigned)(s * STAGE_H) * 2;
        unsigned dA = sb + dstA_off;
        const __half* pA = srcA_base + c * 32;
        cp16(dA, pA);
        cp16(dA + 16, pA + 8);
        unsigned dB = sb + dstB_off;
        const __half* pB = srcB_base + (size_t)c * 32 * 128;
        cp16(dB, pB);
        cp16(dB + 16, pB + 8);
        cp_commit();
    };

    // two chunks in flight before the loop
    load_chunk(0, 0);
    load_chunk(1, 1);

    #pragma unroll
    for (int c = 0; c < 4; ++c) {
        const int s = c & 1;
        // chunk c resident; chunk c+1 may remain in flight
        if (c < 3) cp_wait<1>(); else cp_wait<0>();
        __syncthreads();                 // publish chunk c to all warps

        const unsigned sA0 = sbase + (unsigned)(s * STAGE_H) * 2;
        const unsigned sB0 = sA0 + (unsigned)ABUF * 2;

        #pragma unroll
        for (int ks = 0; ks < 2; ++ks) {
            const int k0 = ks * 16;
            unsigned a[4][4];
            #pragma unroll
            for (int mt = 0; mt < 4; ++mt) {
                unsigned addr = sA0 + ((mw + mt * 16 + lr) * ASK2 + k0 + lc) * 2;
                ldsm_x4(a[mt][0], a[mt][1], a[mt][2], a[mt][3], addr);
            }
            unsigned b[4][2];
            #pragma unroll
            for (int pr = 0; pr < 2; ++pr) {
                unsigned addr = sB0 + ((k0 + lr) * BSK + nw + pr * 16 + lc) * 2;
                unsigned r0, r1, r2, r3;
                ldsm_x4_t(r0, r1, r2, r3, addr);
                b[pr * 2][0] = r0;     b[pr * 2][1] = r1;
                b[pr * 2 + 1][0] = r2; b[pr * 2 + 1][1] = r3;
            }
            #pragma unroll
            for (int mt = 0; mt < 4; ++mt)
                #pragma unroll
                for (int nt = 0; nt < 4; ++nt)
                    mma16816(acc[mt][nt], a[mt], b[nt][0], b[nt][1]);
        }

        if (c < 2) {
            __syncthreads();             // all warps done reading stage s
            load_chunk(c + 2, s);        // refill it with chunk c+2
        }
    }
    __syncthreads();    // all mma reads done before epilogue staging overwrites buffers

    // ---- epilogue: +b1 (u half), fp16, stage through smem, coalesced copy ----
    const int g  = lane >> 2;
    const int t2 = (lane & 3) * 2;
    float bx[4], by[4];
    #pragma unroll
    for (int nt = 0; nt < 4; ++nt) {
        int c0 = nw + nt * 8 + t2;
        bx[nt] = (half == 0) ? b1[c0]     : 0.f;
        by[nt] = (half == 0) ? b1[c0 + 1] : 0.f;
    }

    __half* stage = smem_s;   // 128 x AST(136) halves = 34816 B, fits the pool
    #pragma unroll
    for (int mt = 0; mt < 4; ++mt) {
        #pragma unroll
        for (int nt = 0; nt < 4; ++nt) {
            int row = mw + mt * 16 + g;
            int col = nw + nt * 8 + t2;
            *(__half2*)(stage + row * AST + col) =
                __floats2half2_rn(acc[mt][nt][0] + bx[nt], acc[mt][nt][1] + by[nt]);
            *(__half2*)(stage + (row + 8) * AST + col) =
                __floats2half2_rn(acc[mt][nt][2] + bx[nt], acc[mt][nt][3] + by[nt]);
        }
    }
    __syncthreads();

    #pragma unroll
    for (int rr = 0; rr < 4; ++rr) {
        int r = w * 16 + rr * 4 + (lane >> 3);
        int node = base + r;
        if (node < n_nodes) {
            #pragma unroll
            for (int it = 0; it < 2; ++it) {
                int idx = (lane & 7) + it * 8;
                uint4 val = *(uint4*)(stage + r * AST + idx * 8);
                *(uint4*)(g_uv + (size_t)node * 256 + half * 128 + idx * 8) = val;
            }
        }
    }
}

// ---------------- edge phase v4: fp16 dot, u32 offsets (unchanged) ----------------
__global__ __launch_bounds__(256) void edge_eval(
    const void*  __restrict__ eidx,
    const float* __restrict__ b2,
    float* __restrict__ out,
    int E)
{
    const int lane = threadIdx.x & 31;
    const int hl   = lane & 15;       // feature group (8 features each)
    const int side = lane >> 4;       // which edge of each pair
    const int warp = blockIdx.x * 8 + (threadIdx.x >> 5);
    const long long e0 = (long long)warp * 8;
    if (e0 >= E) return;

    const uint4 w2p = ((const uint4*)g_w2h)[hl];     // 8 fp16 weights for this lane
    const __half2 w0 = bits_h2(w2p.x), w1 = bits_h2(w2p.y);
    const __half2 w2_ = bits_h2(w2p.z), w3 = bits_h2(w2p.w);
    const float  bias = b2[0];
    const int    is64 = g_idx_is64;
    const char* __restrict__ uvb = (const char*)g_uv;   // 512 B per node row

    int nr[4], nc[4];
    if (e0 + 8 <= E && (E & 1) == 0) {
        if (is64) {
            const longlong2* rp = (const longlong2*)eidx;
            #pragma unroll
            for (int t = 0; t < 4; ++t) {
                longlong2 rr = rp[(e0 >> 1) + t];
                nr[t] = (int)(side ? rr.y : rr.x);
                longlong2 cc = rp[(((long long)E + e0) >> 1) + t];
                nc[t] = (int)(side ? cc.y : cc.x);
            }
        } else {
            const int2* rp = (const int2*)eidx;
            #pragma unroll
            for (int t = 0; t < 4; ++t) {
                int2 rr = rp[(e0 >> 1) + t];
                nr[t] = side ? rr.y : rr.x;
                int2 cc = rp[(((long long)E + e0) >> 1) + t];
                nc[t] = side ? cc.y : cc.x;
            }
        }
    } else {
        #pragma unroll
        for (int t = 0; t < 4; ++t) {
            long long e = e0 + 2 * t + side;
            if (e >= E) e = e0;
            if (is64) {
                nr[t] = (int)((const long long*)eidx)[e];
                nc[t] = (int)((const long long*)eidx)[(long long)E + e];
            } else {
                nr[t] = ((const int*)eidx)[e];
                nc[t] = ((const int*)eidx)[(long long)E + e];
            }
        }
    }

    uint4 u[4], v[4];
    const unsigned hloff = (unsigned)hl * 16u;
    #pragma unroll
    for (int t = 0; t < 4; ++t) {
        u[t] = *(const uint4*)(uvb + ((unsigned)nr[t] * 512u + hloff));
        v[t] = *(const uint4*)(uvb + ((unsigned)nc[t] * 512u + 256u + hloff));
    }

    const __half2 z2 = __float2half2_rn(0.f);
    float s[4];
    #pragma unroll
    for (int t = 0; t < 4; ++t) {
        __half2 p0 = __hmax2(__hadd2(bits_h2(u[t].x), bits_h2(v[t].x)), z2);
        __half2 p1 = __hmax2(__hadd2(bits_h2(u[t].y), bits_h2(v[t].y)), z2);
        __half2 p2 = __hmax2(__hadd2(bits_h2(u[t].z), bits_h2(v[t].z)), z2);
        __half2 p3 = __hmax2(__hadd2(bits_h2(u[t].w), bits_h2(v[t].w)), z2);
        __half2 ah = __hmul2(p0, w0);
        ah = __hfma2(p1, w1, ah);
        ah = __hfma2(p2, w2_, ah);
        ah = __hfma2(p3, w3, ah);
        float2 f = __half22float2(ah);
        s[t] = f.x + f.y;
    }

    const unsigned FULLM = 0xffffffffu;
    const bool h8 = (hl & 8);
    float a0, a1;
    {
        float r0 = __shfl_xor_sync(FULLM, h8 ? s[0] : s[2], 8);
        a0 = (h8 ? s[2] : s[0]) + r0;
        float r1 = __shfl_xor_sync(FULLM, h8 ? s[1] : s[3], 8);
        a1 = (h8 ? s[3] : s[1]) + r1;
    }
    const bool h4 = (hl & 4);
    float b;
    {
        float r = __shfl_xor_sync(FULLM, h4 ? a0 : a1, 4);
        b = (h4 ? a1 : a0) + r;
    }
    b += __shfl_xor_sync(FULLM, b, 2);
    b += __shfl_xor_sync(FULLM, b, 1);

    int slot = ((hl >> 3) & 1) * 2 + ((hl >> 2) & 1);
    if ((hl & 3) == 0) {
        long long e = e0 + 2 * slot + side;
        if (e < E) out[e] = b + bias;
    }
}

extern "C" void kernel_launch(void* const* d_in, const int* in_sizes, int n_in,
                              void* d_out, int out_size)
{
    const float* x   = (const float*)d_in[0];
    const void*  ei  = d_in[1];
    const float* W1  = (const float*)d_in[2];
    const float* b1  = (const float*)d_in[3];
    const float* W2  = (const float*)d_in[4];
    const float* b2  = (const float*)d_in[5];
    float* out = (float*)d_out;

    int n_nodes = in_sizes[0] / 128;
    int E = in_sizes[1] / 2;

    long long total4 = (long long)n_nodes * 32;
    int cblocks = (int)((total4 / 2 + 255) / 256);
    convert_fp16<<<cblocks, 256>>>(x, W1, W2, ei, n_nodes);

    dim3 pgrid((n_nodes + 127) / 128, 2);
    precompute_uv<<<pgrid, NT>>>(b1, n_nodes);

    long long warps = ((long long)E + 7) / 8;
    int blocks = (int)((warps + 7) / 8);
    edge_eval<<<blocks, 256>>>(ei, b2, out, E);
}

// round 17
// speedup vs baseline: 1.0003x; 1.0003x over previous
#include <cuda_runtime.h>
#include <cuda_fp16.h>

// LinearEdgeDecoder, factored + fp16 table + HMMA precompute.
// R15 (= R14 resubmit; prior run died to container flake, no kernel signal):
// cp.async pipeline keeps TWO chunks in flight (R13 waited each chunk to
// completion before committing the next, leaving ~1 load-latency exposed).

#define ASK2 40             // A chunk stride in halves (80B rows, ldmatrix conflict-free)
#define BSK  136            // B chunk stride in halves (272B rows)
#define AST  136            // staging stride in halves
#define NT   256
#define ABUF (128 * ASK2)   // 5120 halves per A stage
#define BBUF (32 * BSK)     // 4352 halves per B stage
#define STAGE_H (ABUF + BBUF)

__device__ int    g_idx_is64;
__device__ __align__(16) __half g_uv[(size_t)131072 * 256];   // node table u|v (64 MB)
__device__ __align__(16) __half g_xh[(size_t)131072 * 128];   // x in fp16 (32 MB)
__device__ __align__(16) __half g_wh[256 * 128];              // W1 in fp16
__device__ __align__(16) __half g_w2h[128];                   // W2 in fp16

__device__ __forceinline__ unsigned h2_bits(__half2 h) {
    return *reinterpret_cast<unsigned*>(&h);
}
__device__ __forceinline__ __half2 bits_h2(unsigned b) {
    return *reinterpret_cast<__half2*>(&b);
}

__device__ __forceinline__ void cp16(unsigned dst, const void* src) {
    asm volatile("cp.async.cg.shared.global [%0], [%1], 16;" :: "r"(dst), "l"(src));
}
__device__ __forceinline__ void cp_commit() {
    asm volatile("cp.async.commit_group;");
}
template <int N>
__device__ __forceinline__ void cp_wait() {
    asm volatile("cp.async.wait_group %0;" :: "n"(N));
}

__device__ __forceinline__ void ldsm_x4(unsigned& r0, unsigned& r1, unsigned& r2, unsigned& r3,
                                        unsigned addr) {
    asm volatile("ldmatrix.sync.aligned.m8n8.x4.shared.b16 {%0,%1,%2,%3}, [%4];"
                 : "=r"(r0), "=r"(r1), "=r"(r2), "=r"(r3) : "r"(addr));
}
__device__ __forceinline__ void ldsm_x4_t(unsigned& r0, unsigned& r1, unsigned& r2, unsigned& r3,
                                          unsigned addr) {
    asm volatile("ldmatrix.sync.aligned.m8n8.x4.trans.shared.b16 {%0,%1,%2,%3}, [%4];"
                 : "=r"(r0), "=r"(r1), "=r"(r2), "=r"(r3) : "r"(addr));
}
__device__ __forceinline__ void mma16816(float* c, const unsigned* a, unsigned b0, unsigned b1) {
    asm volatile(
        "mma.sync.aligned.m16n8k16.row.col.f32.f16.f16.f32 "
        "{%0,%1,%2,%3},{%4,%5,%6,%7},{%8,%9},{%0,%1,%2,%3};"
        : "+f"(c[0]), "+f"(c[1]), "+f"(c[2]), "+f"(c[3])
        : "r"(a[0]), "r"(a[1]), "r"(a[2]), "r"(a[3]), "r"(b0), "r"(b1));
}

// ---------------- one-shot fp16 conversion (+ dtype sniff) ----------------
__global__ __launch_bounds__(256) void convert_fp16(
    const float* __restrict__ x,    // [n_nodes, 128]
    const float* __restrict__ W1,   // [256, 128]
    const float* __restrict__ W2,   // [128]
    const void*  __restrict__ eidx,
    int n_nodes)
{
    long long i0 = ((long long)blockIdx.x * 256 + threadIdx.x) * 2;

    if (blockIdx.x == 0 && threadIdx.x < 32) {
        const long long* p = (const long long*)eidx;
        int bad = 0;
        #pragma unroll
        for (int t = 0; t < 2; ++t) {
            long long vv = p[threadIdx.x * 2 + t];
            if (vv < 0 || vv >= (long long)n_nodes) bad = 1;
        }
        unsigned m = __ballot_sync(0xffffffffu, bad);
        if (threadIdx.x == 0) g_idx_is64 = (m == 0u);
    }

    long long total = (long long)n_nodes * 32;   // float4 count of x
    if (i0 + 1 < total) {
        float4 f0 = ((const float4*)x)[i0];
        float4 f1 = ((const float4*)x)[i0 + 1];
        uint4 pk;
        pk.x = h2_bits(__floats2half2_rn(f0.x, f0.y));
        pk.y = h2_bits(__floats2half2_rn(f0.z, f0.w));
        pk.z = h2_bits(__floats2half2_rn(f1.x, f1.y));
        pk.w = h2_bits(__floats2half2_rn(f1.z, f1.w));
        *(uint4*)((uint2*)g_xh + i0) = pk;
    } else if (i0 < total) {
        float4 f0 = ((const float4*)x)[i0];
        uint2 pk;
        pk.x = h2_bits(__floats2half2_rn(f0.x, f0.y));
        pk.y = h2_bits(__floats2half2_rn(f0.z, f0.w));
        ((uint2*)g_xh)[i0] = pk;
    }
    if (i0 < 8192) {                             // W1 = 8192 float4
        #pragma unroll
        for (int t = 0; t < 2; ++t) {
            float4 f = ((const float4*)W1)[i0 + t];
            uint2 pk;
            pk.x = h2_bits(__floats2half2_rn(f.x, f.y));
            pk.y = h2_bits(__floats2half2_rn(f.z, f.w));
            ((uint2*)g_wh)[i0 + t] = pk;
        }
    }
    if (i0 < 32) {                               // W2 = 32 float4
        #pragma unroll
        for (int t = 0; t < 2; ++t) {
            float4 f = ((const float4*)W2)[i0 + t];
            uint2 pk;
            pk.x = h2_bits(__floats2half2_rn(f.x, f.y));
            pk.y = h2_bits(__floats2half2_rn(f.z, f.w));
            ((uint2*)g_w2h)[i0 + t] = pk;
        }
    }
}

// ---------------- node-table GEMM on tensor cores, 2-deep cp.async pipeline ----------------
// grid = (ceil(n_nodes/128), 2). CTA tile 128 nodes x 128 features,
// K=128 as 4 chunks of 32, double-buffered with 2 loads in flight.
__global__ __launch_bounds__(NT) void precompute_uv(
    const float* __restrict__ b1,   // [128]
    int n_nodes)
{
    __shared__ __align__(16) __half smem_s[2 * STAGE_H];   // 37888 B

    const int tid  = threadIdx.x;
    const int base = blockIdx.x * 128;
    const int half = blockIdx.y;     // 0 -> u (+b1), 1 -> v

    const int rA   = tid >> 1;       // node row 0..127
    const int segA = tid & 1;        // 16-half segment within 32-half chunk row
    int nodeA = base + rA; if (nodeA >= n_nodes) nodeA = 0;
    const int rowB  = tid >> 3;      // k row 0..31
    const int laneB = tid & 7;       // 16-half segment within 128-half row

    const int w    = tid >> 5;
    const int lane = tid & 31;
    const int mw   = (w & 1) * 64;
    const int nw   = (w >> 1) * 32;
    const int lr   = lane & 15;
    const int lc   = (lane >> 4) * 8;

    float acc[4][4][4];
    #pragma unroll
    for (int i = 0; i < 4; ++i)
        #pragma unroll
        for (int j = 0; j < 4; ++j)
            #pragma unroll
            for (int t = 0; t < 4; ++t) acc[i][j][t] = 0.f;

    const unsigned sbase = (unsigned)__cvta_generic_to_shared(smem_s);

    const __half* srcA_base = g_xh + (size_t)nodeA * 128 + segA * 16;
    const __half* srcB_base = g_wh + (size_t)(half * 128 + rowB) * 128 + laneB * 16;
    const unsigned dstA_off = (unsigned)(rA * ASK2 + segA * 16) * 2;
    const unsigned dstB_off = (unsigned)(ABUF + rowB * BSK + laneB * 16) * 2;

    auto load_chunk = [&](int c, int s) {
        unsigned sb = sbase + (unsigned)(s * STAGE_H) * 2;
        unsigned dA = sb + dstA_off;
        const __half* pA = srcA_base + c * 32;
        cp16(dA, pA);
        cp16(dA + 16, pA + 8);
        unsigned dB = sb + dstB_off;
        const __half* pB = srcB_base + (size_t)c * 32 * 128;
        cp16(dB, pB);
        cp16(dB + 16, pB + 8);
        cp_commit();
    };

    // two chunks in flight before the loop
    load_chunk(0, 0);
    load_chunk(1, 1);

    #pragma unroll
    for (int c = 0; c < 4; ++c) {
        const int s = c & 1;
        // chunk c resident; chunk c+1 may remain in flight
        if (c < 3) cp_wait<1>(); else cp_wait<0>();
        __syncthreads();                 // publish chunk c to all warps

        const unsigned sA0 = sbase + (unsigned)(s * STAGE_H) * 2;
        const unsigned sB0 = sA0 + (unsigned)ABUF * 2;

        #pragma unroll
        for (int ks = 0; ks < 2; ++ks) {
            const int k0 = ks * 16;
            unsigned a[4][4];
            #pragma unroll
            for (int mt = 0; mt < 4; ++mt) {
                unsigned addr = sA0 + ((mw + mt * 16 + lr) * ASK2 + k0 + lc) * 2;
                ldsm_x4(a[mt][0], a[mt][1], a[mt][2], a[mt][3], addr);
            }
            unsigned b[4][2];
            #pragma unroll
            for (int pr = 0; pr < 2; ++pr) {
                unsigned addr = sB0 + ((k0 + lr) * BSK + nw + pr * 16 + lc) * 2;
                unsigned r0, r1, r2, r3;
                ldsm_x4_t(r0, r1, r2, r3, addr);
                b[pr * 2][0] = r0;     b[pr * 2][1] = r1;
                b[pr * 2 + 1][0] = r2; b[pr * 2 + 1][1] = r3;
            }
            #pragma unroll
            for (int mt = 0; mt < 4; ++mt)
                #pragma unroll
                for (int nt = 0; nt < 4; ++nt)
                    mma16816(acc[mt][nt], a[mt], b[nt][0], b[nt][1]);
        }

        if (c < 2) {
            __syncthreads();             // all warps done reading stage s
            load_chunk(c + 2, s);        // refill it with chunk c+2
        }
    }
    __syncthreads();    // all mma reads done before epilogue staging overwrites buffers

    // ---- epilogue: +b1 (u half), fp16, stage through smem, coalesced copy ----
    const int g  = lane >> 2;
    const int t2 = (lane & 3) * 2;
    float bx[4], by[4];
    #pragma unroll
    for (int nt = 0; nt < 4; ++nt) {
        int c0 = nw + nt * 8 + t2;
        bx[nt] = (half == 0) ? b1[c0]     : 0.f;
        by[nt] = (half == 0) ? b1[c0 + 1] : 0.f;
    }

    __half* stage = smem_s;   // 128 x AST(136) halves = 34816 B, fits the pool
    #pragma unroll
    for (int mt = 0; mt < 4; ++mt) {
        #pragma unroll
        for (int nt = 0; nt < 4; ++nt) {
            int row = mw + mt * 16 + g;
            int col = nw + nt * 8 + t2;
            *(__half2*)(stage + row * AST + col) =
                __floats2half2_rn(acc[mt][nt][0] + bx[nt], acc[mt][nt][1] + by[nt]);
            *(__half2*)(stage + (row + 8) * AST + col) =
                __floats2half2_rn(acc[mt][nt][2] + bx[nt], acc[mt][nt][3] + by[nt]);
        }
    }
    __syncthreads();

    #pragma unroll
    for (int rr = 0; rr < 4; ++rr) {
        int r = w * 16 + rr * 4 + (lane >> 3);
        int node = base + r;
        if (node < n_nodes) {
            #pragma unroll
            for (int it = 0; it < 2; ++it) {
                int idx = (lane & 7) + it * 8;
                uint4 val = *(uint4*)(stage + r * AST + idx * 8);
                *(uint4*)(g_uv + (size_t)node * 256 + half * 128 + idx * 8) = val;
            }
        }
    }
}

// ---------------- edge phase v4: fp16 dot, u32 offsets (unchanged) ----------------
__global__ __launch_bounds__(256) void edge_eval(
    const void*  __restrict__ eidx,
    const float* __restrict__ b2,
    float* __restrict__ out,
    int E)
{
    const int lane = threadIdx.x & 31;
    const int hl   = lane & 15;       // feature group (8 features each)
    const int side = lane >> 4;       // which edge of each pair
    const int warp = blockIdx.x * 8 + (threadIdx.x >> 5);
    const long long e0 = (long long)warp * 8;
    if (e0 >= E) return;

    const uint4 w2p = ((const uint4*)g_w2h)[hl];     // 8 fp16 weights for this lane
    const __half2 w0 = bits_h2(w2p.x), w1 = bits_h2(w2p.y);
    const __half2 w2_ = bits_h2(w2p.z), w3 = bits_h2(w2p.w);
    const float  bias = b2[0];
    const int    is64 = g_idx_is64;
    const char* __restrict__ uvb = (const char*)g_uv;   // 512 B per node row

    int nr[4], nc[4];
    if (e0 + 8 <= E && (E & 1) == 0) {
        if (is64) {
            const longlong2* rp = (const longlong2*)eidx;
            #pragma unroll
            for (int t = 0; t < 4; ++t) {
                longlong2 rr = rp[(e0 >> 1) + t];
                nr[t] = (int)(side ? rr.y : rr.x);
                longlong2 cc = rp[(((long long)E + e0) >> 1) + t];
                nc[t] = (int)(side ? cc.y : cc.x);
            }
        } else {
            const int2* rp = (const int2*)eidx;
            #pragma unroll
            for (int t = 0; t < 4; ++t) {
                int2 rr = rp[(e0 >> 1) + t];
                nr[t] = side ? rr.y : rr.x;
                int2 cc = rp[(((long long)E + e0) >> 1) + t];
                nc[t] = side ? cc.y : cc.x;
            }
        }
    } else {
        #pragma unroll
        for (int t = 0; t < 4; ++t) {
            long long e = e0 + 2 * t + side;
            if (e >= E) e = e0;
            if (is64) {
                nr[t] = (int)((const long long*)eidx)[e];
                nc[t] = (int)((const long long*)eidx)[(long long)E + e];
            } else {
                nr[t] = ((const int*)eidx)[e];
                nc[t] = ((const int*)eidx)[(long long)E + e];
            }
        }
    }

    uint4 u[4], v[4];
    const unsigned hloff = (unsigned)hl * 16u;
    #pragma unroll
    for (int t = 0; t < 4; ++t) {
        u[t] = *(const uint4*)(uvb + ((unsigned)nr[t] * 512u + hloff));
        v[t] = *(const uint4*)(uvb + ((unsigned)nc[t] * 512u + 256u + hloff));
    }

    const __half2 z2 = __float2half2_rn(0.f);
    float s[4];
    #pragma unroll
    for (int t = 0; t < 4; ++t) {
        __half2 p0 = __hmax2(__hadd2(bits_h2(u[t].x), bits_h2(v[t].x)), z2);
        __half2 p1 = __hmax2(__hadd2(bits_h2(u[t].y), bits_h2(v[t].y)), z2);
        __half2 p2 = __hmax2(__hadd2(bits_h2(u[t].z), bits_h2(v[t].z)), z2);
        __half2 p3 = __hmax2(__hadd2(bits_h2(u[t].w), bits_h2(v[t].w)), z2);
        __half2 ah = __hmul2(p0, w0);
        ah = __hfma2(p1, w1, ah);
        ah = __hfma2(p2, w2_, ah);
        ah = __hfma2(p3, w3, ah);
        float2 f = __half22float2(ah);
        s[t] = f.x + f.y;
    }

    const unsigned FULLM = 0xffffffffu;
    const bool h8 = (hl & 8);
    float a0, a1;
    {
        float r0 = __shfl_xor_sync(FULLM, h8 ? s[0] : s[2], 8);
        a0 = (h8 ? s[2] : s[0]) + r0;
        float r1 = __shfl_xor_sync(FULLM, h8 ? s[1] : s[3], 8);
        a1 = (h8 ? s[3] : s[1]) + r1;
    }
    const bool h4 = (hl & 4);
    float b;
    {
        float r = __shfl_xor_sync(FULLM, h4 ? a0 : a1, 4);
        b = (h4 ? a1 : a0) + r;
    }
    b += __shfl_xor_sync(FULLM, b, 2);
    b += __shfl_xor_sync(FULLM, b, 1);

    int slot = ((hl >> 3) & 1) * 2 + ((hl >> 2) & 1);
    if ((hl & 3) == 0) {
        long long e = e0 + 2 * slot + side;
        if (e < E) out[e] = b + bias;
    }
}

extern "C" void kernel_launch(void* const* d_in, const int* in_sizes, int n_in,
                              void* d_out, int out_size)
{
    const float* x   = (const float*)d_in[0];
    const void*  ei  = d_in[1];
    const float* W1  = (const float*)d_in[2];
    const float* b1  = (const float*)d_in[3];
    const float* W2  = (const float*)d_in[4];
    const float* b2  = (const float*)d_in[5];
    float* out = (float*)d_out;

    int n_nodes = in_sizes[0] / 128;
    int E = in_sizes[1] / 2;

    long long total4 = (long long)n_nodes * 32;
    int cblocks = (int)((total4 / 2 + 255) / 256);
    convert_fp16<<<cblocks, 256>>>(x, W1, W2, ei, n_nodes);

    dim3 pgrid((n_nodes + 127) / 128, 2);
    precompute_uv<<<pgrid, NT>>>(b1, n_nodes);

    long long warps = ((long long)E + 7) / 8;
    int blocks = (int)((warps + 7) / 8);
    edge_eval<<<blocks, 256>>>(ei, b2, out, E);
}